// round 2
// baseline (speedup 1.0000x reference)
#include <cuda_runtime.h>
#include <cuda_bf16.h>
#include <cstdint>

#define KDIM 1024
#define IDIM 64
#define ODIM 1024
#define THREADS 256
#define KC 64                 // fp32 k per chunk
#define NCHUNK (KDIM / KC)    // 16
#define ROWB 144              // padded bf16 tile row: 64 bf16 (128B) + 16B pad

// SMEM offsets (bytes, from dynamic smem base)
#define OFF_AH 0
#define OFF_AL (128 * ROWB)          // 18432
#define OFF_BH (2 * 128 * ROWB)      // 36864
#define OFF_BL (3 * 128 * ROWB)      // 55296
#define OFF_STG (4 * 128 * ROWB)     // 73728
#define STG_SZ (2 * 128 * KC * 4)    // 65536 (A fp32 32KB + B fp32 32KB)
#define STG_B_OFF (128 * KC * 4)     // 32768 within a stage buffer
#define SMEM_DYN (OFF_STG + 2 * STG_SZ)  // 204800

static __device__ __forceinline__ uint32_t smem_u32(const void* p) {
    uint32_t a;
    asm("{ .reg .u64 t; cvta.to.shared.u64 t, %1; cvt.u32.u64 %0, t; }"
        : "=r"(a) : "l"(p));
    return a;
}

static __device__ __forceinline__ void ldm_x4(uint32_t* r, uint32_t addr) {
    asm volatile(
        "ldmatrix.sync.aligned.m8n8.x4.shared.b16 {%0,%1,%2,%3}, [%4];"
        : "=r"(r[0]), "=r"(r[1]), "=r"(r[2]), "=r"(r[3]) : "r"(addr));
}

static __device__ __forceinline__ void mma_bf16(float* d, const uint32_t* a,
                                                const uint32_t* b) {
    asm volatile(
        "mma.sync.aligned.m16n8k16.row.col.f32.bf16.bf16.f32 "
        "{%0,%1,%2,%3}, {%4,%5,%6,%7}, {%8,%9}, {%0,%1,%2,%3};"
        : "+f"(d[0]), "+f"(d[1]), "+f"(d[2]), "+f"(d[3])
        : "r"(a[0]), "r"(a[1]), "r"(a[2]), "r"(a[3]), "r"(b[0]), "r"(b[1]));
}

static __device__ __forceinline__ void cp16(uint32_t saddr, const void* gaddr) {
    asm volatile("cp.async.cg.shared.global [%0], [%1], 16;"
                 :: "r"(saddr), "l"(gaddr));
}

// Issue cp.async for one K-chunk: A tile [128 x 64] f32 and B tile [128 x 64] f32.
// Row stride in gmem is 65536 floats (= IDIM*KDIM) for both x and w views.
static __device__ __forceinline__ void stage_chunk(uint32_t stg,
                                                   const float* __restrict__ ga,
                                                   const float* __restrict__ gb) {
    const int tid = threadIdx.x;
#pragma unroll
    for (int it = 0; it < 8; ++it) {
        int f = tid + it * THREADS;          // float4 index, 0..2047
        int row = f >> 4;
        int c4 = f & 15;
        cp16(stg + (uint32_t)(row * 256 + c4 * 16),
             ga + (size_t)row * 65536 + c4 * 4);
        cp16(stg + STG_B_OFF + (uint32_t)(row * 256 + c4 * 16),
             gb + (size_t)row * 65536 + c4 * 4);
    }
    asm volatile("cp.async.commit_group;" ::: "memory");
}

// Convert one staged fp32 tile pair into bf16 hi/lo padded tiles.
static __device__ __forceinline__ void convert_stage(char* sm, uint32_t stg_off) {
    const int tid = threadIdx.x;
    const float* stA = (const float*)(sm + stg_off);
    const float* stB = (const float*)(sm + stg_off + STG_B_OFF);
#pragma unroll
    for (int it = 0; it < 8; ++it) {
        int f = tid + it * THREADS;
        int row = f >> 4;
        int c4 = f & 15;
        uint32_t dst = (uint32_t)(row * ROWB + c4 * 8);
#pragma unroll
        for (int ab = 0; ab < 2; ++ab) {
            const float4 v = *reinterpret_cast<const float4*>(
                (ab ? stB : stA) + (row * 64 + c4 * 4));
            __nv_bfloat16 h0 = __float2bfloat16_rn(v.x);
            __nv_bfloat16 h1 = __float2bfloat16_rn(v.y);
            __nv_bfloat16 h2 = __float2bfloat16_rn(v.z);
            __nv_bfloat16 h3 = __float2bfloat16_rn(v.w);
            __nv_bfloat16 l0 = __float2bfloat16_rn(v.x - __bfloat162float(h0));
            __nv_bfloat16 l1 = __float2bfloat16_rn(v.y - __bfloat162float(h1));
            __nv_bfloat16 l2 = __float2bfloat16_rn(v.z - __bfloat162float(h2));
            __nv_bfloat16 l3 = __float2bfloat16_rn(v.w - __bfloat162float(h3));
            uint32_t hi01 = (uint32_t)__bfloat16_as_ushort(h0) |
                            ((uint32_t)__bfloat16_as_ushort(h1) << 16);
            uint32_t hi23 = (uint32_t)__bfloat16_as_ushort(h2) |
                            ((uint32_t)__bfloat16_as_ushort(h3) << 16);
            uint32_t lo01 = (uint32_t)__bfloat16_as_ushort(l0) |
                            ((uint32_t)__bfloat16_as_ushort(l1) << 16);
            uint32_t lo23 = (uint32_t)__bfloat16_as_ushort(l2) |
                            ((uint32_t)__bfloat16_as_ushort(l3) << 16);
            int offH = ab ? OFF_BH : OFF_AH;
            int offL = ab ? OFF_BL : OFF_AL;
            *reinterpret_cast<uint2*>(sm + offH + dst) = make_uint2(hi01, hi23);
            *reinterpret_cast<uint2*>(sm + offL + dst) = make_uint2(lo01, lo23);
        }
    }
}

__global__ void __launch_bounds__(THREADS)
fl_kernel(const float* __restrict__ x, const float* __restrict__ w,
          const float* __restrict__ bias, float* __restrict__ out) {
    extern __shared__ char sm[];
    const uint32_t sbase = smem_u32(sm);
    const int tid = threadIdx.x;
    const int wid = tid >> 5;
    const int lid = tid & 31;
    const int warp_m = wid >> 2;   // 0..1 : 64 rows of M each
    const int warp_n = wid & 3;    // 0..3 : 32 cols of N each
    const int otile = blockIdx.x;  // 0..7
    const int i_idx = blockIdx.y;  // 0..63

    const float* xa = x + (size_t)i_idx * KDIM;
    const float* wa = w + ((size_t)otile * 128) * (IDIM * KDIM) + (size_t)i_idx * KDIM;

    float acc[4][4][4];
#pragma unroll
    for (int a = 0; a < 4; ++a)
#pragma unroll
        for (int b = 0; b < 4; ++b)
#pragma unroll
            for (int c = 0; c < 4; ++c) acc[a][b][c] = 0.0f;

    // Prologue: stage chunks 0 and 1
    stage_chunk(sbase + OFF_STG, xa, wa);
    stage_chunk(sbase + OFF_STG + STG_SZ, xa + KC, wa + KC);

    // Precompute ldmatrix lane address components
    const uint32_t a_row = (uint32_t)(warp_m * 64 + (lid & 15));
    const uint32_t a_cb = (uint32_t)((lid >> 4) * 16);
    const uint32_t b_row = (uint32_t)(warp_n * 32 + ((lid >> 4) << 3) + (lid & 7));
    const uint32_t b_cb = (uint32_t)(((lid >> 3) & 1) * 16);

    for (int ch = 0; ch < NCHUNK; ++ch) {
        asm volatile("cp.async.wait_group 1;" ::: "memory");
        __syncthreads();

        const uint32_t stg_off = (uint32_t)(OFF_STG + (ch & 1) * STG_SZ);
        convert_stage(sm, stg_off);
        __syncthreads();

        // Prefetch chunk ch+2 into the buffer we just consumed
        if (ch + 2 < NCHUNK) {
            stage_chunk(sbase + stg_off, xa + (ch + 2) * KC, wa + (ch + 2) * KC);
        } else {
            asm volatile("cp.async.commit_group;" ::: "memory");
        }

        // MMA over this chunk's 4 K=16 steps
#pragma unroll
        for (int ks = 0; ks < 4; ++ks) {
            uint32_t ah[4][4], al[4][4], bh[2][4], bl[2][4];
#pragma unroll
            for (int mt = 0; mt < 4; ++mt) {
                uint32_t addr = sbase + OFF_AH +
                                (a_row + mt * 16) * ROWB + ks * 32 + a_cb;
                ldm_x4(ah[mt], addr);
                ldm_x4(al[mt], addr + (OFF_AL - OFF_AH));
            }
#pragma unroll
            for (int bt = 0; bt < 2; ++bt) {
                uint32_t addr = sbase + OFF_BH +
                                (b_row + bt * 16) * ROWB + ks * 32 + b_cb;
                ldm_x4(bh[bt], addr);
                ldm_x4(bl[bt], addr + (OFF_BL - OFF_BH));
            }
#pragma unroll
            for (int mt = 0; mt < 4; ++mt) {
#pragma unroll
                for (int nt = 0; nt < 4; ++nt) {
                    const uint32_t* bhp = &bh[nt >> 1][(nt & 1) * 2];
                    const uint32_t* blp = &bl[nt >> 1][(nt & 1) * 2];
                    mma_bf16(acc[mt][nt], ah[mt], bhp);   // hi*hi
                    mma_bf16(acc[mt][nt], ah[mt], blp);   // hi*lo
                    mma_bf16(acc[mt][nt], al[mt], bhp);   // lo*hi
                }
            }
        }
        __syncthreads();   // protect bf16 tiles before next convert
    }

    // Epilogue: add bias, store. out[b][o][i] = b*65536 + o*64 + i
    const float* bp = bias + (size_t)(otile * 128) * IDIM + i_idx;
    float bv[4][2];
#pragma unroll
    for (int nt = 0; nt < 4; ++nt) {
        int n_l = warp_n * 32 + nt * 8 + 2 * (lid & 3);
        bv[nt][0] = bp[(size_t)n_l * IDIM];
        bv[nt][1] = bp[(size_t)(n_l + 1) * IDIM];
    }
#pragma unroll
    for (int mt = 0; mt < 4; ++mt) {
        int m0 = warp_m * 64 + mt * 16 + (lid >> 2);
#pragma unroll
        for (int nt = 0; nt < 4; ++nt) {
            int n_l = warp_n * 32 + nt * 8 + 2 * (lid & 3);
            float* o0 = out + (size_t)m0 * (ODIM * IDIM) +
                        (size_t)(otile * 128 + n_l) * IDIM + i_idx;
            o0[0] = acc[mt][nt][0] + bv[nt][0];
            o0[IDIM] = acc[mt][nt][1] + bv[nt][1];
            float* o8 = o0 + (size_t)8 * (ODIM * IDIM);
            o8[0] = acc[mt][nt][2] + bv[nt][0];
            o8[IDIM] = acc[mt][nt][3] + bv[nt][1];
        }
    }
}

extern "C" void kernel_launch(void* const* d_in, const int* in_sizes, int n_in,
                              void* d_out, int out_size) {
    (void)in_sizes; (void)n_in; (void)out_size;
    const float* x = (const float*)d_in[0];
    const float* w = (const float*)d_in[1];
    const float* bias = (const float*)d_in[2];
    float* out = (float*)d_out;

    cudaFuncSetAttribute(fl_kernel, cudaFuncAttributeMaxDynamicSharedMemorySize,
                         SMEM_DYN);
    fl_kernel<<<dim3(ODIM / 128, IDIM), THREADS, SMEM_DYN>>>(x, w, bias, out);
}